// round 1
// baseline (speedup 1.0000x reference)
#include <cuda_runtime.h>
#include <cuda_bf16.h>

#define BATCH 4096
#define NA 8
#define ND 11
#define NPOS 3584
#define NPAIR 1792          // NPOS/2
#define ATOM 512
#define NS 4096
#define ROWS 32768          // BATCH*NA
#define DPAD 12             // ND padded to even

// Packed normalized positions: [pair][d] as float2 {pos[2p][d], pos[2p+1][d]},
// d padded to 12 (pad = 0). Total 1792*12*8 = 172032 bytes = 10752 float4.
__device__ float4 g_pos2[NPAIR * 6];
__device__ int g_idx[ROWS];

// ---- packed f32x2 helpers (sm_100a; ptxas never emits these from C++) ----
static __device__ __forceinline__ unsigned long long pack2(float lo, float hi) {
    unsigned long long r;
    asm("mov.b64 %0, {%1, %2};" : "=l"(r) : "f"(lo), "f"(hi));
    return r;
}
static __device__ __forceinline__ void unpack2(unsigned long long v, float& lo, float& hi) {
    asm("mov.b64 {%0, %1}, %2;" : "=f"(lo), "=f"(hi) : "l"(v));
}
static __device__ __forceinline__ unsigned long long mul2(unsigned long long a, unsigned long long b) {
    unsigned long long r;
    asm("mul.rn.f32x2 %0, %1, %2;" : "=l"(r) : "l"(a), "l"(b));
    return r;
}
static __device__ __forceinline__ unsigned long long fma2(unsigned long long a, unsigned long long b,
                                                          unsigned long long c) {
    unsigned long long r;
    asm("fma.rn.f32x2 %0, %1, %2, %3;" : "=l"(r) : "l"(a), "l"(b), "l"(c));
    return r;
}

// ---- Phase 0: normalize positions, pack into pair-of-positions f32x2 layout ----
__global__ void prep_kernel(const float* __restrict__ positions) {
    int p = blockIdx.x * blockDim.x + threadIdx.x;
    if (p >= NPOS) return;
    float v[ND];
    float acc = 0.0f;
#pragma unroll
    for (int d = 0; d < ND; d++) {
        v[d] = positions[p * ND + d];
        acc = fmaf(v[d], v[d], acc);
    }
    float nrm = sqrtf(acc);
    float* dst = (float*)g_pos2;
    int pair = p >> 1;
    int half = p & 1;
#pragma unroll
    for (int d = 0; d < ND; d++) dst[pair * (2 * DPAD) + d * 2 + half] = v[d] / nrm;
    dst[pair * (2 * DPAD) + 2 * ND + half] = 0.0f;  // pad d = 11
}

// ---- Phase 1: cosine-sim argmax. One thread per (b,a) row; all normalized
// positions resident in SMEM (172 KB, 1 CTA/SM); 4 positions per iteration via
// two independent 11-deep fma.f32x2 chains. Strict '>' + ascending p reproduces
// jnp.argmax first-max tie-breaking. ----
__global__ void __launch_bounds__(224, 1) argmax_kernel(const float* __restrict__ index,
                                                        float* __restrict__ out_idx) {
    extern __shared__ float4 s4[];
    // cooperative load of the whole packed position table
    for (int i = threadIdx.x; i < NPAIR * 6; i += blockDim.x) s4[i] = g_pos2[i];
    __syncthreads();

    int row = blockIdx.x * blockDim.x + threadIdx.x;
    if (row >= ROWS) return;

    // normalize this query row (same op order as reference)
    float iv[ND];
    float acc = 0.0f;
#pragma unroll
    for (int d = 0; d < ND; d++) {
        iv[d] = index[row * ND + d];
        acc = fmaf(iv[d], iv[d], acc);
    }
    float nrm = sqrtf(acc);
    unsigned long long ind2[ND];
#pragma unroll
    for (int d = 0; d < ND; d++) {
        float h = iv[d] / nrm;
        ind2[d] = pack2(h, h);
    }

    const ulonglong2* s = (const ulonglong2*)s4;
    float best = -2.0f;
    int bi = 0;

    for (int p2 = 0; p2 < NPAIR; p2 += 2) {
        const ulonglong2* pp = s + p2 * 6;
        unsigned long long pa[DPAD], pb[DPAD];
#pragma unroll
        for (int j = 0; j < 6; j++) {
            ulonglong2 q = pp[j];
            pa[2 * j] = q.x;
            pa[2 * j + 1] = q.y;
        }
#pragma unroll
        for (int j = 0; j < 6; j++) {
            ulonglong2 q = pp[6 + j];
            pb[2 * j] = q.x;
            pb[2 * j + 1] = q.y;
        }
        unsigned long long sA = mul2(ind2[0], pa[0]);
        unsigned long long sB = mul2(ind2[0], pb[0]);
#pragma unroll
        for (int d = 1; d < ND; d++) {
            sA = fma2(ind2[d], pa[d], sA);
            sB = fma2(ind2[d], pb[d], sB);
        }
        float s0, s1, s2, s3;
        unpack2(sA, s0, s1);
        unpack2(sB, s2, s3);
        int p = p2 * 2;
        if (s0 > best) { best = s0; bi = p; }
        if (s1 > best) { best = s1; bi = p + 1; }
        if (s2 > best) { best = s2; bi = p + 2; }
        if (s3 > best) { best = s3; bi = p + 3; }
    }

    out_idx[row] = (float)bi;
    g_idx[row] = bi;
}

// ---- Phase 2: overlap-add scatter. One CTA per batch row, SMEM accumulator. ----
__global__ void scatter_kernel(const float* __restrict__ atoms, float* __restrict__ out) {
    __shared__ __align__(16) float buf[NS];
    int b = blockIdx.x;
    for (int i = threadIdx.x; i < NS; i += blockDim.x) buf[i] = 0.0f;
    __syncthreads();
#pragma unroll
    for (int a = 0; a < NA; a++) {
        int off = g_idx[b * NA + a];
        for (int t = threadIdx.x; t < ATOM; t += blockDim.x)
            buf[off + t] += atoms[a * ATOM + t];
        __syncthreads();
    }
    float4* o = (float4*)(out + (size_t)b * NS);
    const float4* bf = (const float4*)buf;
    for (int i = threadIdx.x; i < NS / 4; i += blockDim.x) o[i] = bf[i];
}

extern "C" void kernel_launch(void* const* d_in, const int* in_sizes, int n_in,
                              void* d_out, int out_size) {
    const float* index = (const float*)d_in[0];      // (4096, 8, 11)
    const float* positions = (const float*)d_in[1];  // (3584, 11)
    const float* atoms = (const float*)d_in[2];      // (8, 512)
    float* out = (float*)d_out;  // [int_index(32768) | output(16777216) | index(360448)]

    prep_kernel<<<(NPOS + 127) / 128, 128>>>(positions);

    const size_t smem = (size_t)NPAIR * 6 * sizeof(float4);  // 172032 B
    cudaFuncSetAttribute(argmax_kernel, cudaFuncAttributeMaxDynamicSharedMemorySize, (int)smem);
    argmax_kernel<<<148, 224, smem>>>(index, out);

    scatter_kernel<<<BATCH, 256>>>(atoms, out + ROWS);

    cudaMemcpyAsync(out + ROWS + (size_t)BATCH * NS, index,
                    (size_t)ROWS * ND * sizeof(float), cudaMemcpyDeviceToDevice);
}

// round 2
// speedup vs baseline: 1.0509x; 1.0509x over previous
#include <cuda_runtime.h>
#include <cuda_bf16.h>

#define BATCH 4096
#define NA 8
#define ND 11
#define NPOS 3584
#define NPAIR 1792          // NPOS/2
#define ATOM 512
#define NS 4096
#define ROWS 32768          // BATCH*NA
#define DPAD 12             // ND padded to even

#define NSPLIT 7            // position chunks
#define CHUNK 256           // pairs per chunk  (7*256 = 1792)
#define RPT 4               // rows per thread
#define ATHREADS 128        // argmax block size
#define RB (ATHREADS * RPT) // rows per CTA = 512
#define NRB (ROWS / RB)     // 64 row-blocks

// Packed normalized positions: [pair][d] as float2 {pos[2p][d], pos[2p+1][d]},
// d padded to 12 (pad = 0). 1792*12*8 = 172032 bytes.
__device__ float4 g_pos2[NPAIR * 6];
// per-row packed (ordered_sim << 32 | (NPOS-1-idx)); merged via atomicMax
__device__ unsigned long long g_key[ROWS];

// ---- packed f32x2 helpers ----
static __device__ __forceinline__ unsigned long long pack2(float lo, float hi) {
    unsigned long long r;
    asm("mov.b64 %0, {%1, %2};" : "=l"(r) : "f"(lo), "f"(hi));
    return r;
}
static __device__ __forceinline__ void unpack2(unsigned long long v, float& lo, float& hi) {
    asm("mov.b64 {%0, %1}, %2;" : "=f"(lo), "=f"(hi) : "l"(v));
}
static __device__ __forceinline__ unsigned long long mul2(unsigned long long a, unsigned long long b) {
    unsigned long long r;
    asm("mul.rn.f32x2 %0, %1, %2;" : "=l"(r) : "l"(a), "l"(b));
    return r;
}
static __device__ __forceinline__ unsigned long long fma2(unsigned long long a, unsigned long long b,
                                                          unsigned long long c) {
    unsigned long long r;
    asm("fma.rn.f32x2 %0, %1, %2, %3;" : "=l"(r) : "l"(a), "l"(b), "l"(c));
    return r;
}

// ---- Phase 0: normalize+pack positions, zero the merge keys (re-run every replay) ----
__global__ void prep_kernel(const float* __restrict__ positions) {
    int t = blockIdx.x * blockDim.x + threadIdx.x;  // 32768 threads
    if (t < ROWS) g_key[t] = 0ull;
    if (t >= NPOS) return;
    float v[ND];
    float acc = 0.0f;
#pragma unroll
    for (int d = 0; d < ND; d++) {
        v[d] = positions[t * ND + d];
        acc = fmaf(v[d], v[d], acc);
    }
    float nrm = sqrtf(acc);
    float* dst = (float*)g_pos2;
    int pair = t >> 1;
    int half = t & 1;
#pragma unroll
    for (int d = 0; d < ND; d++) dst[pair * (2 * DPAD) + d * 2 + half] = v[d] / nrm;
    dst[pair * (2 * DPAD) + 2 * ND + half] = 0.0f;
}

// ---- Phase 1: cosine-sim argmax, (row-block, pos-chunk) 2D decomposition.
// R=4 rows per thread -> 4 independent fma.f32x2 chains, position pair LDS
// amortized 4x. Chunk-local best tracked with strict '>' ascending scan;
// cross-chunk merge via atomicMax on (ordered_sim, NPOS-1-idx) key which
// preserves first-max tie-breaking. ----
__global__ void __launch_bounds__(ATHREADS, 3) argmax_kernel(const float* __restrict__ index) {
    __shared__ __align__(16) float4 s4[CHUNK * 6];
    int rb = blockIdx.x / NSPLIT;
    int ch = blockIdx.x % NSPLIT;

    for (int i = threadIdx.x; i < CHUNK * 6; i += ATHREADS)
        s4[i] = g_pos2[ch * (CHUNK * 6) + i];
    __syncthreads();

    const int r0 = rb * RB + threadIdx.x * RPT;

    // load + normalize RPT query rows (same op order as reference)
    unsigned long long q[RPT][ND];
#pragma unroll
    for (int rr = 0; rr < RPT; rr++) {
        const float* ip = index + (size_t)(r0 + rr) * ND;
        float iv[ND];
        float acc = 0.0f;
#pragma unroll
        for (int d = 0; d < ND; d++) {
            iv[d] = ip[d];
            acc = fmaf(iv[d], iv[d], acc);
        }
        float nrm = sqrtf(acc);
#pragma unroll
        for (int d = 0; d < ND; d++) {
            float h = iv[d] / nrm;
            q[rr][d] = pack2(h, h);
        }
    }

    float best[RPT];
    int bi[RPT];
#pragma unroll
    for (int rr = 0; rr < RPT; rr++) { best[rr] = -2.0f; bi[rr] = 0; }

    const ulonglong2* s = (const ulonglong2*)s4;
    const int pbase = ch * CHUNK * 2;

    for (int p2 = 0; p2 < CHUNK; p2++) {
        unsigned long long pa[DPAD];
        const ulonglong2* pp = s + p2 * 6;
#pragma unroll
        for (int j = 0; j < 6; j++) {
            ulonglong2 w = pp[j];
            pa[2 * j] = w.x;
            pa[2 * j + 1] = w.y;
        }
        int p = pbase + p2 * 2;
#pragma unroll
        for (int rr = 0; rr < RPT; rr++) {
            unsigned long long sA = mul2(q[rr][0], pa[0]);
#pragma unroll
            for (int d = 1; d < ND; d++) sA = fma2(q[rr][d], pa[d], sA);
            float s0, s1;
            unpack2(sA, s0, s1);
            if (s0 > best[rr]) { best[rr] = s0; bi[rr] = p; }
            if (s1 > best[rr]) { best[rr] = s1; bi[rr] = p + 1; }
        }
    }

#pragma unroll
    for (int rr = 0; rr < RPT; rr++) {
        unsigned ub = __float_as_uint(best[rr]);
        ub = (ub & 0x80000000u) ? ~ub : (ub | 0x80000000u);
        unsigned long long key =
            ((unsigned long long)ub << 32) | (unsigned)(NPOS - 1 - bi[rr]);
        atomicMax(&g_key[r0 + rr], key);
    }
}

// ---- Phase 2: decode keys, write int_index section, overlap-add scatter ----
__global__ void scatter_kernel(const float* __restrict__ atoms, float* __restrict__ out) {
    __shared__ __align__(16) float buf[NS];
    __shared__ int offs[NA];
    int b = blockIdx.x;
    if (threadIdx.x < NA) {
        unsigned long long k = g_key[b * NA + threadIdx.x];
        int idx = NPOS - 1 - (int)(unsigned)(k & 0xFFFFFFFFull);
        offs[threadIdx.x] = idx;
        out[b * NA + threadIdx.x] = (float)idx;  // int_index section
    }
    for (int i = threadIdx.x; i < NS; i += blockDim.x) buf[i] = 0.0f;
    __syncthreads();
    float* obase = out + ROWS;  // output section
#pragma unroll
    for (int a = 0; a < NA; a++) {
        int off = offs[a];
        for (int t = threadIdx.x; t < ATOM; t += blockDim.x)
            buf[off + t] += atoms[a * ATOM + t];
        __syncthreads();
    }
    float4* o = (float4*)(obase + (size_t)b * NS);
    const float4* bf = (const float4*)buf;
    for (int i = threadIdx.x; i < NS / 4; i += blockDim.x) o[i] = bf[i];
}

extern "C" void kernel_launch(void* const* d_in, const int* in_sizes, int n_in,
                              void* d_out, int out_size) {
    const float* index = (const float*)d_in[0];      // (4096, 8, 11)
    const float* positions = (const float*)d_in[1];  // (3584, 11)
    const float* atoms = (const float*)d_in[2];      // (8, 512)
    float* out = (float*)d_out;  // [int_index(32768) | output(16777216) | index(360448)]

    // independent passthrough copy first
    cudaMemcpyAsync(out + ROWS + (size_t)BATCH * NS, index,
                    (size_t)ROWS * ND * sizeof(float), cudaMemcpyDeviceToDevice);

    prep_kernel<<<ROWS / 256, 256>>>(positions);

    argmax_kernel<<<NRB * NSPLIT, ATHREADS>>>(index);

    scatter_kernel<<<BATCH, 256>>>(atoms, out);
}

// round 4
// speedup vs baseline: 1.3977x; 1.3301x over previous
#include <cuda_runtime.h>
#include <cuda_fp16.h>
#include <cstdint>

#define BATCH 4096
#define NA 8
#define ND 11
#define NPOS 3584
#define ATOM 512
#define NS 4096
#define ROWS 32768          // BATCH*NA
#define NTILES 448          // NPOS/8
#define NRB 2048            // ROWS/16 row-blocks
#define INV4096 (1.0f/4096.0f)
#define INV2P24 (1.0f/16777216.0f)

// Per-lane mma fragments, packed by prep:
//  A (row-major 16x16): g_Afh/g_Afl[rb*32+lane] = {a0,a1,a2,a3}
//  B (col 16x8):        g_Bf[nt*32+lane]        = {b0h,b1h,b0l,b1l}
__device__ uint4 g_Afh[NRB * 32], g_Afl[NRB * 32];
__device__ uint4 g_Bf[NTILES * 32];
__device__ int g_idx[ROWS];

static __device__ __forceinline__ uint32_t h2pack(float x, float y) {
    __half2 h = __halves2half2(__float2half_rn(x), __float2half_rn(y));
    return *(uint32_t*)&h;
}

// ---- Phase 0: normalize (reference op order), fp16 hi/lo split, fragment pack ----
__global__ void prep_kernel(const float* __restrict__ index, const float* __restrict__ positions) {
    int t = blockIdx.x * blockDim.x + threadIdx.x;
    int g, tig;
    if (t < NRB * 32) {  // A fragments
        int rb = t >> 5, lane = t & 31;
        g = lane >> 2; tig = lane & 3;
        float h[2][16], l[2][16];
#pragma unroll
        for (int rr = 0; rr < 2; rr++) {
            int row = rb * 16 + g + rr * 8;
            const float* ip = index + (size_t)row * ND;
            float v[ND], acc = 0.0f;
#pragma unroll
            for (int d = 0; d < ND; d++) { v[d] = ip[d]; acc = fmaf(v[d], v[d], acc); }
            float nrm = sqrtf(acc);
#pragma unroll
            for (int d = 0; d < 16; d++) {
                float f = (d < ND) ? (v[d] / nrm) : 0.0f;
                float hi = __half2float(__float2half_rn(f));
                h[rr][d] = hi;
                l[rr][d] = (f - hi) * 4096.0f;
            }
        }
        int k0 = tig * 2;
        g_Afh[t] = make_uint4(h2pack(h[0][k0], h[0][k0 + 1]), h2pack(h[1][k0], h[1][k0 + 1]),
                              h2pack(h[0][k0 + 8], h[0][k0 + 9]), h2pack(h[1][k0 + 8], h[1][k0 + 9]));
        g_Afl[t] = make_uint4(h2pack(l[0][k0], l[0][k0 + 1]), h2pack(l[1][k0], l[1][k0 + 1]),
                              h2pack(l[0][k0 + 8], l[0][k0 + 9]), h2pack(l[1][k0 + 8], l[1][k0 + 9]));
    } else if (t < NRB * 32 + NTILES * 32) {  // B fragments
        int tt = t - NRB * 32;
        int nt = tt >> 5, lane = tt & 31;
        g = lane >> 2; tig = lane & 3;
        int p = nt * 8 + g;
        const float* pp = positions + (size_t)p * ND;
        float v[ND], acc = 0.0f;
#pragma unroll
        for (int d = 0; d < ND; d++) { v[d] = pp[d]; acc = fmaf(v[d], v[d], acc); }
        float nrm = sqrtf(acc);
        float h[16], l[16];
#pragma unroll
        for (int d = 0; d < 16; d++) {
            float f = (d < ND) ? (v[d] / nrm) : 0.0f;
            float hi = __half2float(__float2half_rn(f));
            h[d] = hi;
            l[d] = (f - hi) * 4096.0f;
        }
        int k0 = tig * 2;
        g_Bf[tt] = make_uint4(h2pack(h[k0], h[k0 + 1]), h2pack(h[k0 + 8], h[k0 + 9]),
                              h2pack(l[k0], l[k0 + 1]), h2pack(l[k0 + 8], l[k0 + 9]));
    }
}

static __device__ __forceinline__ void mma16816(float d[4], const uint4& a, uint32_t b0,
                                                uint32_t b1, const float c[4]) {
    asm volatile(
        "mma.sync.aligned.m16n8k16.row.col.f32.f16.f16.f32 "
        "{%0,%1,%2,%3}, {%4,%5,%6,%7}, {%8,%9}, {%10,%11,%12,%13};"
        : "=f"(d[0]), "=f"(d[1]), "=f"(d[2]), "=f"(d[3])
        : "r"(a.x), "r"(a.y), "r"(a.z), "r"(a.w), "r"(b0), "r"(b1),
          "f"(c[0]), "f"(c[1]), "f"(c[2]), "f"(c[3]));
}

// ---- Phase 1: split-fp16 mma GEMM + in-register streaming argmax ----
// One warp owns 16 rows x all 3584 positions. 4 mma per 16x8 tile:
//   Dh = AhBh; Dl = AhBl + AlBh; Dll = AlBl; sim = Dh + Dl/2^12 + Dll/2^24
__global__ void __launch_bounds__(256) argmax_kernel(float* __restrict__ out_idx) {
    const int lane = threadIdx.x & 31;
    const int warp = (blockIdx.x << 3) + (threadIdx.x >> 5);  // = rb
    const int g = lane >> 2, tig = lane & 3;

    const uint4 Ah = g_Afh[warp * 32 + lane];
    const uint4 Al = g_Afl[warp * 32 + lane];

    float best0 = -1e30f, best1 = -1e30f;
    int bi0 = 0, bi1 = 0;
    const float zc[4] = {0.f, 0.f, 0.f, 0.f};

#pragma unroll 4
    for (int nt = 0; nt < NTILES; nt++) {
        uint4 B = g_Bf[nt * 32 + lane];
        float dh[4], dl[4], dll[4];
        mma16816(dh, Ah, B.x, B.y, zc);
        mma16816(dl, Ah, B.z, B.w, zc);
        mma16816(dl, Al, B.x, B.y, dl);
        mma16816(dll, Al, B.z, B.w, zc);

        float s0 = fmaf(dll[0], INV2P24, fmaf(dl[0], INV4096, dh[0]));
        float s1 = fmaf(dll[1], INV2P24, fmaf(dl[1], INV4096, dh[1]));
        float s2 = fmaf(dll[2], INV2P24, fmaf(dl[2], INV4096, dh[2]));
        float s3 = fmaf(dll[3], INV2P24, fmaf(dl[3], INV4096, dh[3]));

        int p = nt * 8 + tig * 2;
        float m0 = fmaxf(s0, s1);
        if (m0 > best0) { best0 = m0; bi0 = (s1 > s0) ? p + 1 : p; }
        float m1 = fmaxf(s2, s3);
        if (m1 > best1) { best1 = m1; bi1 = (s3 > s2) ? p + 1 : p; }
    }

    // reduce across the 4 lanes (tig) sharing each row; tie-break = smaller index
    unsigned u0 = __float_as_uint(best0);
    u0 = (u0 & 0x80000000u) ? ~u0 : (u0 | 0x80000000u);
    unsigned u1 = __float_as_uint(best1);
    u1 = (u1 & 0x80000000u) ? ~u1 : (u1 | 0x80000000u);
    unsigned long long k0 = ((unsigned long long)u0 << 32) | (unsigned)(NPOS - 1 - bi0);
    unsigned long long k1 = ((unsigned long long)u1 << 32) | (unsigned)(NPOS - 1 - bi1);
#pragma unroll
    for (int s = 1; s <= 2; s <<= 1) {
        unsigned long long o0 = __shfl_xor_sync(0xFFFFFFFFu, k0, s);
        unsigned long long o1 = __shfl_xor_sync(0xFFFFFFFFu, k1, s);
        if (o0 > k0) k0 = o0;
        if (o1 > k1) k1 = o1;
    }
    if (tig == 0) {
        int row0 = warp * 16 + g, row1 = row0 + 8;
        int i0 = NPOS - 1 - (int)(unsigned)(k0 & 0xFFFFFFFFull);
        int i1 = NPOS - 1 - (int)(unsigned)(k1 & 0xFFFFFFFFull);
        out_idx[row0] = (float)i0;
        out_idx[row1] = (float)i1;
        g_idx[row0] = i0;
        g_idx[row1] = i1;
    }
}

// ---- Phase 2: overlap-add scatter ----
__global__ void scatter_kernel(const float* __restrict__ atoms, float* __restrict__ out) {
    __shared__ __align__(16) float buf[NS];
    int b = blockIdx.x;
    for (int i = threadIdx.x; i < NS; i += blockDim.x) buf[i] = 0.0f;
    __syncthreads();
#pragma unroll
    for (int a = 0; a < NA; a++) {
        int off = g_idx[b * NA + a];
        for (int t = threadIdx.x; t < ATOM; t += blockDim.x)
            buf[off + t] += atoms[a * ATOM + t];
        __syncthreads();
    }
    float4* o = (float4*)(out + (size_t)b * NS);
    const float4* bf = (const float4*)buf;
    for (int i = threadIdx.x; i < NS / 4; i += blockDim.x) o[i] = bf[i];
}

extern "C" void kernel_launch(void* const* d_in, const int* in_sizes, int n_in,
                              void* d_out, int out_size) {
    const float* index = (const float*)d_in[0];      // (4096, 8, 11)
    const float* positions = (const float*)d_in[1];  // (3584, 11)
    const float* atoms = (const float*)d_in[2];      // (8, 512)
    float* out = (float*)d_out;  // [int_index(32768) | output(16777216) | index(360448)]

    cudaMemcpyAsync(out + ROWS + (size_t)BATCH * NS, index,
                    (size_t)ROWS * ND * sizeof(float), cudaMemcpyDeviceToDevice);

    prep_kernel<<<(NRB * 32 + NTILES * 32 + 255) / 256, 256>>>(index, positions);

    argmax_kernel<<<NRB / 8, 256>>>(out);

    scatter_kernel<<<BATCH, 256>>>(atoms, out + ROWS);
}

// round 5
// speedup vs baseline: 1.4998x; 1.0730x over previous
#include <cuda_runtime.h>
#include <cuda_fp16.h>
#include <cstdint>

#define BATCH 4096
#define NA 8
#define ND 11
#define NPOS 3584
#define ATOM 512
#define NS 4096
#define ROWS 32768          // BATCH*NA
#define NTILES 448          // NPOS/8
#define NRB 2048            // ROWS/16 row-blocks
#define CTILES 64           // tiles per SMEM chunk (32 KB)
#define NCH 7               // NTILES/CTILES
#define INV4096 (1.0f/4096.0f)
#define INV2P24 (1.0f/16777216.0f)

// Per-lane mma fragments, packed by prep:
//  A (row-major 16x16): g_Afh/g_Afl[rb*32+lane] = {a0,a1,a2,a3}
//  B (col 16x8):        g_Bf[nt*32+lane]        = {b0h,b1h,b0l,b1l}
__device__ uint4 g_Afh[NRB * 32], g_Afl[NRB * 32];
__device__ uint4 g_Bf[NTILES * 32];
__device__ int g_idx[ROWS];

static __device__ __forceinline__ uint32_t h2pack(float x, float y) {
    __half2 h = __halves2half2(__float2half_rn(x), __float2half_rn(y));
    return *(uint32_t*)&h;
}
static __device__ __forceinline__ uint32_t smem_u32(const void* p) {
    uint32_t a;
    asm("{ .reg .u64 t; cvta.to.shared.u64 t, %1; cvt.u32.u64 %0, t; }" : "=r"(a) : "l"(p));
    return a;
}
#define CP_ASYNC16(smem, gmem) \
    asm volatile("cp.async.cg.shared.global [%0], [%1], 16;" :: "r"(smem), "l"(gmem) : "memory")
#define CP_COMMIT() asm volatile("cp.async.commit_group;" ::: "memory")
#define CP_WAIT(n)  asm volatile("cp.async.wait_group %0;" :: "n"(n) : "memory")

// ---- Phase 0: normalize (reference op order), fp16 hi/lo split, fragment pack,
//      and fold in the raw-index passthrough write ----
__global__ void prep_kernel(const float* __restrict__ index, const float* __restrict__ positions,
                            float* __restrict__ out_pass) {
    int t = blockIdx.x * blockDim.x + threadIdx.x;
    if (t < NRB * 32) {  // A fragments
        int rb = t >> 5, lane = t & 31;
        int g = lane >> 2, tig = lane & 3;
        float h[2][16], l[2][16];
#pragma unroll
        for (int rr = 0; rr < 2; rr++) {
            int row = rb * 16 + g + rr * 8;
            const float* ip = index + (size_t)row * ND;
            float v[ND], acc = 0.0f;
#pragma unroll
            for (int d = 0; d < ND; d++) { v[d] = ip[d]; acc = fmaf(v[d], v[d], acc); }
            if (tig == 0) {  // passthrough of raw values (one lane per row)
                float* op = out_pass + (size_t)row * ND;
#pragma unroll
                for (int d = 0; d < ND; d++) op[d] = v[d];
            }
            float nrm = sqrtf(acc);
#pragma unroll
            for (int d = 0; d < 16; d++) {
                float f = (d < ND) ? (v[d] / nrm) : 0.0f;
                float hi = __half2float(__float2half_rn(f));
                h[rr][d] = hi;
                l[rr][d] = (f - hi) * 4096.0f;
            }
        }
        int k0 = tig * 2;
        g_Afh[t] = make_uint4(h2pack(h[0][k0], h[0][k0 + 1]), h2pack(h[1][k0], h[1][k0 + 1]),
                              h2pack(h[0][k0 + 8], h[0][k0 + 9]), h2pack(h[1][k0 + 8], h[1][k0 + 9]));
        g_Afl[t] = make_uint4(h2pack(l[0][k0], l[0][k0 + 1]), h2pack(l[1][k0], l[1][k0 + 1]),
                              h2pack(l[0][k0 + 8], l[0][k0 + 9]), h2pack(l[1][k0 + 8], l[1][k0 + 9]));
    } else if (t < NRB * 32 + NTILES * 32) {  // B fragments
        int tt = t - NRB * 32;
        int nt = tt >> 5, lane = tt & 31;
        int g = lane >> 2, tig = lane & 3;
        int p = nt * 8 + g;
        const float* pp = positions + (size_t)p * ND;
        float v[ND], acc = 0.0f;
#pragma unroll
        for (int d = 0; d < ND; d++) { v[d] = pp[d]; acc = fmaf(v[d], v[d], acc); }
        float nrm = sqrtf(acc);
        float h[16], l[16];
#pragma unroll
        for (int d = 0; d < 16; d++) {
            float f = (d < ND) ? (v[d] / nrm) : 0.0f;
            float hi = __half2float(__float2half_rn(f));
            h[d] = hi;
            l[d] = (f - hi) * 4096.0f;
        }
        int k0 = tig * 2;
        g_Bf[tt] = make_uint4(h2pack(h[k0], h[k0 + 1]), h2pack(h[k0 + 8], h[k0 + 9]),
                              h2pack(l[k0], l[k0 + 1]), h2pack(l[k0 + 8], l[k0 + 9]));
    }
}

static __device__ __forceinline__ void mma16816(float d[4], const uint4& a, uint32_t b0,
                                                uint32_t b1, const float c[4]) {
    asm volatile(
        "mma.sync.aligned.m16n8k16.row.col.f32.f16.f16.f32 "
        "{%0,%1,%2,%3}, {%4,%5,%6,%7}, {%8,%9}, {%10,%11,%12,%13};"
        : "=f"(d[0]), "=f"(d[1]), "=f"(d[2]), "=f"(d[3])
        : "r"(a.x), "r"(a.y), "r"(a.z), "r"(a.w), "r"(b0), "r"(b1),
          "f"(c[0]), "f"(c[1]), "f"(c[2]), "f"(c[3]));
}

// ---- Phase 1: split-fp16 mma GEMM + in-register streaming argmax.
// One warp owns 16 rows x all positions. B staged through a 64 KB SMEM double
// buffer with cp.async (8 warps share each chunk -> 8x less L2 traffic). ----
__global__ void __launch_bounds__(256, 1) argmax_kernel(float* __restrict__ out_idx) {
    extern __shared__ uint4 sB[];  // [2][CTILES*32]
    const int tid = threadIdx.x;
    const int lane = tid & 31;
    const int warp = (blockIdx.x << 3) + (tid >> 5);  // row-block id
    const int g = lane >> 2, tig = lane & 3;
    const uint32_t sb0 = smem_u32(sB);

    const uint4 Ah = g_Afh[warp * 32 + lane];
    const uint4 Al = g_Afl[warp * 32 + lane];

    // issue chunk 0
    {
        const uint4* src = g_Bf;
#pragma unroll
        for (int i = 0; i < 8; i++) {
            int idx = tid + i * 256;
            CP_ASYNC16(sb0 + (uint32_t)idx * 16u, src + idx);
        }
        CP_COMMIT();
    }

    float best0 = -1e30f, best1 = -1e30f;
    int bi0 = 0, bi1 = 0;
    const float zc[4] = {0.f, 0.f, 0.f, 0.f};

    for (int c = 0; c < NCH; c++) {
        if (c + 1 < NCH) {  // prefetch next chunk into the other buffer
            const uint4* src = g_Bf + (size_t)(c + 1) * (CTILES * 32);
            uint32_t dst = sb0 + (uint32_t)(((c + 1) & 1) * (CTILES * 32) * 16);
#pragma unroll
            for (int i = 0; i < 8; i++) {
                int idx = tid + i * 256;
                CP_ASYNC16(dst + (uint32_t)idx * 16u, src + idx);
            }
            CP_COMMIT();
            CP_WAIT(1);
        } else {
            CP_WAIT(0);
        }
        __syncthreads();

        const uint4* bb = sB + (c & 1) * (CTILES * 32);
        int pbase = c * CTILES * 8 + tig * 2;
#pragma unroll 4
        for (int t = 0; t < CTILES; t++) {
            uint4 B = bb[t * 32 + lane];
            float dh[4], dl[4], dll[4];
            mma16816(dh, Ah, B.x, B.y, zc);
            mma16816(dl, Ah, B.z, B.w, zc);
            mma16816(dl, Al, B.x, B.y, dl);
            mma16816(dll, Al, B.z, B.w, zc);

            float s0 = fmaf(dll[0], INV2P24, fmaf(dl[0], INV4096, dh[0]));
            float s1 = fmaf(dll[1], INV2P24, fmaf(dl[1], INV4096, dh[1]));
            float s2 = fmaf(dll[2], INV2P24, fmaf(dl[2], INV4096, dh[2]));
            float s3 = fmaf(dll[3], INV2P24, fmaf(dl[3], INV4096, dh[3]));

            int p = pbase + t * 8;
            float m0 = fmaxf(s0, s1);
            if (m0 > best0) { best0 = m0; bi0 = (s1 > s0) ? p + 1 : p; }
            float m1 = fmaxf(s2, s3);
            if (m1 > best1) { best1 = m1; bi1 = (s3 > s2) ? p + 1 : p; }
        }
        __syncthreads();
    }

    // reduce across the 4 lanes (tig) sharing each row; tie-break = smaller index
    unsigned u0 = __float_as_uint(best0);
    u0 = (u0 & 0x80000000u) ? ~u0 : (u0 | 0x80000000u);
    unsigned u1 = __float_as_uint(best1);
    u1 = (u1 & 0x80000000u) ? ~u1 : (u1 | 0x80000000u);
    unsigned long long k0 = ((unsigned long long)u0 << 32) | (unsigned)(NPOS - 1 - bi0);
    unsigned long long k1 = ((unsigned long long)u1 << 32) | (unsigned)(NPOS - 1 - bi1);
#pragma unroll
    for (int s = 1; s <= 2; s <<= 1) {
        unsigned long long o0 = __shfl_xor_sync(0xFFFFFFFFu, k0, s);
        unsigned long long o1 = __shfl_xor_sync(0xFFFFFFFFu, k1, s);
        if (o0 > k0) k0 = o0;
        if (o1 > k1) k1 = o1;
    }
    if (tig == 0) {
        int row0 = warp * 16 + g, row1 = row0 + 8;
        int i0 = NPOS - 1 - (int)(unsigned)(k0 & 0xFFFFFFFFull);
        int i1 = NPOS - 1 - (int)(unsigned)(k1 & 0xFFFFFFFFull);
        out_idx[row0] = (float)i0;
        out_idx[row1] = (float)i1;
        g_idx[row0] = i0;
        g_idx[row1] = i1;
    }
}

// ---- Phase 2: overlap-add scatter ----
__global__ void scatter_kernel(const float* __restrict__ atoms, float* __restrict__ out) {
    __shared__ __align__(16) float buf[NS];
    int b = blockIdx.x;
    for (int i = threadIdx.x; i < NS; i += blockDim.x) buf[i] = 0.0f;
    __syncthreads();
#pragma unroll
    for (int a = 0; a < NA; a++) {
        int off = g_idx[b * NA + a];
        for (int t = threadIdx.x; t < ATOM; t += blockDim.x)
            buf[off + t] += atoms[a * ATOM + t];
        __syncthreads();
    }
    float4* o = (float4*)(out + (size_t)b * NS);
    const float4* bf = (const float4*)buf;
    for (int i = threadIdx.x; i < NS / 4; i += blockDim.x) o[i] = bf[i];
}

extern "C" void kernel_launch(void* const* d_in, const int* in_sizes, int n_in,
                              void* d_out, int out_size) {
    const float* index = (const float*)d_in[0];      // (4096, 8, 11)
    const float* positions = (const float*)d_in[1];  // (3584, 11)
    const float* atoms = (const float*)d_in[2];      // (8, 512)
    float* out = (float*)d_out;  // [int_index(32768) | output(16777216) | index(360448)]

    prep_kernel<<<(NRB * 32 + NTILES * 32 + 255) / 256, 256>>>(
        index, positions, out + ROWS + (size_t)BATCH * NS);

    const int smem = 2 * CTILES * 32 * sizeof(uint4);  // 65536 B
    cudaFuncSetAttribute(argmax_kernel, cudaFuncAttributeMaxDynamicSharedMemorySize, smem);
    argmax_kernel<<<NRB / 8, 256, smem>>>(out);

    scatter_kernel<<<BATCH, 256>>>(atoms, out + ROWS);
}